// round 9
// baseline (speedup 1.0000x reference)
#include <cuda_runtime.h>
#include <math.h>

#define B 4
#define H 16
#define T 8192
#define D 64
#define C 64
#define W 128
#define NC 64
#define BH (B*H)

// ---------------- scratch (static device globals; no runtime alloc) ----------------
__device__ float g_knorm[(size_t)B*H*T*D];   // 134 MB
__device__ float g_dists[(size_t)B*H*C*T];   // 134 MB, layout (b,h,c,t)
__device__ int   g_buckets[B*H*T];
__device__ float g_part[(size_t)B*H*C*D];    // per-b partial sums, layout ((b,h,c),d)
__device__ int   g_bins[H*C];
__device__ float g_meansu[H*C*D];
__device__ int   g_indices[B*H*T];
__device__ int   g_count[B*H*T];

// ---------------- K0: zero accumulators ----------------
__global__ void k_zero(float* __restrict__ out) {
    size_t i = (size_t)blockIdx.x * blockDim.x + threadIdx.x;
    size_t stride = (size_t)gridDim.x * blockDim.x;
    const size_t NOUT = (size_t)B*H*T*D;
    for (size_t p = i; p < NOUT; p += stride) out[p] = 0.f;
    for (size_t p = i; p < (size_t)B*H*T; p += stride) g_count[p] = 0;
    for (size_t p = i; p < (size_t)H*C; p += stride) g_bins[p] = 0;
}

// ---------------- K1: k_norm = l2norm(qk), bit-exact vs XLA-CPU lowering ----------------
// one THREAD per token: ssq = sequential d-ascending FUSED fma chain
// (FPOpFusion::Fast fuses x*x into the accumulate on the reference backend),
// n = max(sqrt(ssq), 1e-12), y_d = x_d / n  (true IEEE division).
__global__ void k_norm(const float* __restrict__ qk) {
    int tok = blockIdx.x * blockDim.x + threadIdx.x;
    if (tok >= B*H*T) return;
    const float4* src = (const float4*)(qk + (size_t)tok * D);
    float v[64];
    #pragma unroll
    for (int i = 0; i < 16; i++) {
        float4 q = src[i];
        v[4*i+0] = q.x; v[4*i+1] = q.y; v[4*i+2] = q.z; v[4*i+3] = q.w;
    }
    float s = 0.f;
    #pragma unroll
    for (int d = 0; d < 64; d++) s = __fmaf_rn(v[d], v[d], s);
    float n = fmaxf(__fsqrt_rn(s), 1e-12f);
    float4* dst = (float4*)(g_knorm + (size_t)tok * D);
    #pragma unroll
    for (int i = 0; i < 16; i++) {
        float4 o;
        o.x = __fdiv_rn(v[4*i+0], n);
        o.y = __fdiv_rn(v[4*i+1], n);
        o.z = __fdiv_rn(v[4*i+2], n);
        o.w = __fdiv_rn(v[4*i+3], n);
        dst[i] = o;
    }
}

// ---------------- K2: buckets = argmax_c (k_norm . means), fma chain ascending d ----------------
__global__ void k_buckets(const float* __restrict__ means) {
    __shared__ float sM[C*D];
    __shared__ float sT[64*65];
    int blk = blockIdx.x;
    int bh = blk / (T/64);
    int chunk = blk % (T/64);
    int h = bh % H;
    for (int i = threadIdx.x; i < C*D; i += 64) sM[i] = means[(size_t)h*C*D + i];
    size_t base = ((size_t)bh*T + (size_t)chunk*64) * D;
    for (int i = threadIdx.x; i < 64*D; i += 64) {
        int r = i >> 6, d = i & 63;
        sT[r*65 + d] = g_knorm[base + i];
    }
    __syncthreads();
    int t0 = threadIdx.x;
    float best = -1e30f; int bi = 0;
    for (int c = 0; c < C; c++) {
        float s = 0.f;
        #pragma unroll
        for (int d = 0; d < D; d++) s = __fmaf_rn(sT[t0*65 + d], sM[c*D + d], s);
        if (s > best) { best = s; bi = c; }   // strict > keeps first index on ties
    }
    g_buckets[(size_t)bh*T + chunk*64 + t0] = bi;
}

// ---------------- K3a: per-(b,h,c) partial sums, STRICT t-ascending order ----------------
// one warp per (b,h,c). All lanes scan t sequentially; lane owns dims 2L,2L+1.
// Matches deterministic scatter-add update order (row-major over (b,h,t)).
__global__ void k_sumsA() {
    int inst = blockIdx.x;                 // (b*H + h)*C + c
    int b = inst >> 10;                    // /(H*C)
    int hc = inst & 1023;
    int c = hc & 63;
    int lane = threadIdx.x;
    size_t base = ((size_t)(b*H) + (hc >> 6)) * T;
    const int* bkt = g_buckets + base;
    float ax = 0.f, ay = 0.f;
    int cnt = 0;
    for (int t = 0; t < T; t += 8) {
        int bk[8];
        #pragma unroll
        for (int u = 0; u < 8; u++) bk[u] = __ldg(&bkt[t+u]);
        #pragma unroll
        for (int u = 0; u < 8; u++) {
            if (bk[u] == c) {
                float2 xv = ((const float2*)(g_knorm + (base + t + u) * D))[lane];
                ax = __fadd_rn(ax, xv.x);
                ay = __fadd_rn(ay, xv.y);
                cnt++;
            }
        }
    }
    float2 o; o.x = ax; o.y = ay;
    ((float2*)(g_part + (size_t)inst * D))[lane] = o;
    if (lane == 0) atomicAdd(&g_bins[hc], cnt);
}

// ---------------- K4: means_upd: b-ascending combine + FUSED sequential ssq + division ----------------
__global__ void k_meansupd(const float* __restrict__ means) {
    int inst = blockIdx.x * blockDim.x + threadIdx.x;   // h*C + c
    if (inst >= H*C) return;
    float sv[64];
    #pragma unroll 4
    for (int d = 0; d < D; d++) {
        float s = g_part[((size_t)0*1024 + inst)*D + d];
        s = __fadd_rn(s, g_part[((size_t)1*1024 + inst)*D + d]);
        s = __fadd_rn(s, g_part[((size_t)2*1024 + inst)*D + d]);
        s = __fadd_rn(s, g_part[((size_t)3*1024 + inst)*D + d]);
        sv[d] = s;
    }
    float ssq = 0.f;
    #pragma unroll
    for (int d = 0; d < D; d++) ssq = __fmaf_rn(sv[d], sv[d], ssq);
    float n = fmaxf(__fsqrt_rn(ssq), 1e-12f);
    bool empty = (g_bins[inst] == 0);
    #pragma unroll 4
    for (int d = 0; d < D; d++) {
        float o = empty ? means[(size_t)inst*D + d] : __fdiv_rn(sv[d], n);
        g_meansu[(size_t)inst*D + d] = o;
    }
}

// ---------------- K5: dists (b,h,c,t) = k_norm . means_upd^T, fma chain ascending d ----------------
__global__ void k_dists() {
    __shared__ float sM[C*D];
    __shared__ float sT[64*65];
    int blk = blockIdx.x;
    int bh = blk / (T/64);
    int chunk = blk % (T/64);
    int h = bh % H;
    int tid = threadIdx.x;
    for (int i = tid; i < C*D; i += 128) sM[i] = g_meansu[(size_t)h*C*D + i];
    size_t base = ((size_t)bh*T + (size_t)chunk*64) * D;
    for (int i = tid; i < 64*D; i += 128) {
        int r = i >> 6, d = i & 63;
        sT[r*65 + d] = g_knorm[base + i];
    }
    __syncthreads();
    int tok = tid & 63;
    int half = tid >> 6;
    for (int cc = half; cc < C; cc += 2) {
        float s = 0.f;
        #pragma unroll
        for (int d = 0; d < D; d++) s = __fmaf_rn(sT[tok*65 + d], sM[cc*D + d], s);
        g_dists[((size_t)bh*C + cc)*T + (size_t)chunk*64 + tok] = s;
    }
}

// ---------------- K6: top-128 per (b,h,c): radix select + bitonic index sort ----------------
__global__ void k_topk() {
    __shared__ unsigned int keys[T];        // 32 KB
    __shared__ unsigned int hist[256];
    __shared__ unsigned int sh_pref;
    __shared__ int sh_k;
    __shared__ int outbuf[W];
    __shared__ int gtc;
    __shared__ int eqbase;
    __shared__ int warpTot[8];

    int inst = blockIdx.x;                  // (b*H+h)*C + c
    int bh = inst / C;
    int c = inst % C;
    int tid = threadIdx.x, lane = tid & 31, wid = tid >> 5;

    const float* row = g_dists + (size_t)inst * T;
    for (int i = tid; i < T; i += 256) {
        unsigned int u = __float_as_uint(row[i]);
        keys[i] = (u & 0x80000000u) ? ~u : (u | 0x80000000u);  // monotone float->uint
    }
    __syncthreads();

    unsigned int prefix = 0; int k = 128;
    for (int sh = 24; sh >= 0; sh -= 8) {
        hist[tid] = 0;
        __syncthreads();
        unsigned int hmask = (sh == 24) ? 0u : (0xFFFFFFFFu << (sh + 8));
        for (int i = tid; i < T; i += 256) {
            unsigned int kk = keys[i];
            if ((kk & hmask) == prefix) atomicAdd(&hist[(kk >> sh) & 255], 1u);
        }
        __syncthreads();
        if (tid == 0) {
            int cum = 0;
            for (int bkt = 255; bkt >= 0; bkt--) {
                cum += (int)hist[bkt];
                if (cum >= k) {
                    sh_pref = prefix | ((unsigned int)bkt << sh);
                    sh_k = k - (cum - (int)hist[bkt]);
                    break;
                }
            }
        }
        __syncthreads();
        prefix = sh_pref; k = sh_k;
        __syncthreads();
    }
    unsigned int Tkey = prefix;
    int k_rem = k;
    int count_gt = 128 - k_rem;

    if (tid == 0) { gtc = 0; eqbase = 0; }
    __syncthreads();

    for (int i = tid; i < T; i += 256) {
        if (keys[i] > Tkey) {
            int p = atomicAdd(&gtc, 1);
            outbuf[p] = i;
        }
    }
    __syncthreads();

    for (int ch = 0; ch < T; ch += 256) {
        int i = ch + tid;
        bool eq = (keys[i] == Tkey);
        unsigned int bal = __ballot_sync(0xffffffffu, eq);
        int wpre = __popc(bal & ((1u << lane) - 1u));
        if (lane == 0) warpTot[wid] = __popc(bal);
        __syncthreads();
        int base = eqbase;
        int woff = 0;
        for (int w = 0; w < wid; w++) woff += warpTot[w];
        if (eq) {
            int rank = base + woff + wpre;
            if (rank < k_rem) outbuf[count_gt + rank] = i;
        }
        __syncthreads();
        if (tid == 0) {
            int tot = 0;
            for (int w = 0; w < 8; w++) tot += warpTot[w];
            eqbase += tot;
        }
        __syncthreads();
        if (eqbase >= k_rem) break;
    }

    for (int size = 2; size <= 128; size <<= 1) {
        for (int stride = size >> 1; stride > 0; stride >>= 1) {
            __syncthreads();
            if (tid < 128) {
                int partner = tid ^ stride;
                if (partner > tid) {
                    bool up = ((tid & size) == 0);
                    int a = outbuf[tid], b2 = outbuf[partner];
                    if ((a > b2) == up) { outbuf[tid] = b2; outbuf[partner] = a; }
                }
            }
        }
    }
    __syncthreads();
    if (tid < 128) g_indices[(size_t)bh*T + c*W + tid] = outbuf[tid];
}

// ---------------- K7: windowed attention + scatter ----------------
#define ATTN_SMEM ((128*64 + 128*65 + 128*64 + 128*65) * 4 + 128 * 4)

__global__ __launch_bounds__(256, 1)
void k_attn(const float* __restrict__ qk, const float* __restrict__ v,
            const float* __restrict__ rw, float* __restrict__ out) {
    extern __shared__ float sm[];
    float* sQ = sm;                      // [128][64]
    float* sK = sQ + 128*64;             // [128][65]
    float* sV = sK + 128*65;             // [128][64]
    float* sR = sV + 128*64;             // [128][65]
    int*   sIdx = (int*)(sR + 128*65);

    int inst = blockIdx.x;
    int bh = inst / NC;
    int n  = inst % NC;
    int h  = bh % H;
    int tid = threadIdx.x, lane = tid & 31, wid = tid >> 5;

    if (tid < 128) sIdx[tid] = g_indices[(size_t)bh*T + n*W + tid];
    __syncthreads();

    for (int r = wid; r < 128; r += 8) {
        int g = sIdx[r];
        size_t off = ((size_t)bh*T + g) * D;
        float2 a = ((const float2*)(qk + off))[lane];
        float2 b2 = ((const float2*)(g_knorm + off))[lane];
        float2 c2 = ((const float2*)(v + off))[lane];
        sQ[r*64 + 2*lane] = a.x;  sQ[r*64 + 2*lane + 1] = a.y;
        sK[r*65 + 2*lane] = b2.x; sK[r*65 + 2*lane + 1] = b2.y;
        sV[r*64 + 2*lane] = c2.x; sV[r*64 + 2*lane + 1] = c2.y;
        float2 rr = ((const float2*)(rw + ((size_t)r*H + h)*D))[lane];
        sR[r*65 + 2*lane] = rr.x; sR[r*65 + 2*lane + 1] = rr.y;
    }
    __syncthreads();

    const float scale = 0.125f;

    for (int p = 0; p < 8; p++) {
        int i0 = wid + 16*p;
        int i1 = i0 + 8;
        float a0[4], a1[4];
        #pragma unroll
        for (int jj = 0; jj < 4; jj++) { a0[jj] = 0.f; a1[jj] = 0.f; }

        for (int d = 0; d < D; d++) {
            float q0 = sQ[i0*64 + d];
            float q1 = sQ[i1*64 + d];
            #pragma unroll
            for (int jj = 0; jj < 4; jj++) {
                float kv = sK[(lane + 32*jj)*65 + d];
                a0[jj] += q0 * kv;
                a1[jj] += q1 * kv;
            }
        }
        #pragma unroll
        for (int jj = 0; jj < 4; jj++) {
            int j = lane + 32*jj;
            if (j < i0) {
                int r = 127 + j - i0;
                float s = 0.f;
                for (int d = 0; d < D; d++) s += sQ[i0*64 + d] * sR[r*65 + d];
                a0[jj] += s;
            }
            if (j < i1) {
                int r = 127 + j - i1;
                float s = 0.f;
                for (int d = 0; d < D; d++) s += sQ[i1*64 + d] * sR[r*65 + d];
                a1[jj] += s;
            }
        }

        float p0[4], p1[4];
        {
            float m = -1e30f;
            #pragma unroll
            for (int jj = 0; jj < 4; jj++) {
                int j = lane + 32*jj;
                a0[jj] = (j == i0) ? -50000.0f : a0[jj]*scale;
                m = fmaxf(m, a0[jj]);
            }
            #pragma unroll
            for (int o = 16; o; o >>= 1) m = fmaxf(m, __shfl_xor_sync(0xffffffffu, m, o));
            float s = 0.f;
            #pragma unroll
            for (int jj = 0; jj < 4; jj++) { p0[jj] = expf(a0[jj] - m); s += p0[jj]; }
            #pragma unroll
            for (int o = 16; o; o >>= 1) s += __shfl_xor_sync(0xffffffffu, s, o);
            float inv = 1.0f / s;
            #pragma unroll
            for (int jj = 0; jj < 4; jj++) p0[jj] *= inv;
        }
        {
            float m = -1e30f;
            #pragma unroll
            for (int jj = 0; jj < 4; jj++) {
                int j = lane + 32*jj;
                a1[jj] = (j == i1) ? -50000.0f : a1[jj]*scale;
                m = fmaxf(m, a1[jj]);
            }
            #pragma unroll
            for (int o = 16; o; o >>= 1) m = fmaxf(m, __shfl_xor_sync(0xffffffffu, m, o));
            float s = 0.f;
            #pragma unroll
            for (int jj = 0; jj < 4; jj++) { p1[jj] = expf(a1[jj] - m); s += p1[jj]; }
            #pragma unroll
            for (int o = 16; o; o >>= 1) s += __shfl_xor_sync(0xffffffffu, s, o);
            float inv = 1.0f / s;
            #pragma unroll
            for (int jj = 0; jj < 4; jj++) p1[jj] *= inv;
        }

        float o00 = 0.f, o01 = 0.f, o10 = 0.f, o11 = 0.f;
        #pragma unroll
        for (int jj = 0; jj < 4; jj++) {
            for (int js = 0; js < 32; js++) {
                float w0 = __shfl_sync(0xffffffffu, p0[jj], js);
                float w1 = __shfl_sync(0xffffffffu, p1[jj], js);
                float2 vv = ((const float2*)(sV + (jj*32 + js)*64))[lane];
                o00 += w0 * vv.x; o01 += w0 * vv.y;
                o10 += w1 * vv.x; o11 += w1 * vv.y;
            }
        }

        {
            int g = sIdx[i0];
            float* dst = out + ((size_t)bh*T + g)*D + 2*lane;
            atomicAdd(dst,     o00);
            atomicAdd(dst + 1, o01);
            if (lane == 0) atomicAdd(&g_count[(size_t)bh*T + g], 1);
        }
        {
            int g = sIdx[i1];
            float* dst = out + ((size_t)bh*T + g)*D + 2*lane;
            atomicAdd(dst,     o10);
            atomicAdd(dst + 1, o11);
            if (lane == 0) atomicAdd(&g_count[(size_t)bh*T + g], 1);
        }
    }
}

// ---------------- K8: finalize out /= (count + 1e-5) ----------------
__global__ void k_final(float* __restrict__ out) {
    size_t i = (size_t)blockIdx.x * blockDim.x + threadIdx.x;
    size_t stride = (size_t)gridDim.x * blockDim.x;
    const size_t N = (size_t)B*H*T*D;
    for (size_t p = i; p < N; p += stride) {
        float cnt = (float)g_count[p >> 6];
        out[p] = out[p] / (cnt + 1e-5f);
    }
}

// ---------------- launch ----------------
extern "C" void kernel_launch(void* const* d_in, const int* in_sizes, int n_in,
                              void* d_out, int out_size) {
    const float* qk    = (const float*)d_in[0];
    const float* v     = (const float*)d_in[1];
    const float* means = (const float*)d_in[2];
    const float* rw    = (const float*)d_in[3];
    float* out = (float*)d_out;

    cudaFuncSetAttribute(k_attn, cudaFuncAttributeMaxDynamicSharedMemorySize, ATTN_SMEM);

    k_zero<<<2048, 256>>>(out);
    k_norm<<<(B*H*T + 255)/256, 256>>>(qk);
    k_buckets<<<BH*(T/64), 64>>>(means);
    k_sumsA<<<B*H*C, 32>>>();
    k_meansupd<<<(H*C + 255)/256, 256>>>(means);
    k_dists<<<BH*(T/64), 128>>>();
    k_topk<<<BH*C, 256>>>();
    k_attn<<<BH*NC, 256, ATTN_SMEM>>>(qk, v, rw, out);
    k_final<<<4096, 256>>>(out);
}